// round 1
// baseline (speedup 1.0000x reference)
#include <cuda_runtime.h>

// SymLoss: B=32 samples, Flow/Mask (B,2,512,512) f32, A/B axes (B,2) f32.
// loss = (1/B) * sum_b  num_b / denom_b
//   num_b   = sum_{c,y,x} mask[c,y,x] * sq[y,x] * valid[y,x]
//   sq      = (dphi1*b0 - dphi0*b1)^2, dphi = flow - bilinear_shift(flow)
//   denom_b = 2 * max(hp,1) * max(x_hi-x_lo,1)

#define HH 512
#define WW 512
#define BN 32

__global__ void sym_zero_out(float* out) { out[0] = 0.0f; }

__global__ __launch_bounds__(256) void symloss_kernel(
    const float* __restrict__ Flow,
    const float* __restrict__ Asym,
    const float* __restrict__ Bsym,
    const float* __restrict__ Mask,
    float* __restrict__ out)
{
    const int b    = blockIdx.y;
    const int row0 = blockIdx.x * 8;

    // ---- per-sample params (cheap, computed by every thread) ----
    const float a0  = __ldg(Asym + 2 * b);
    const float a1  = __ldg(Asym + 2 * b + 1);
    const float sb0 = __ldg(Bsym + 2 * b);
    const float sb1 = __ldg(Bsym + 2 * b + 1);

    const float dxf = -3.0f * a0;
    const float dyf = fabsf(3.0f * a1);
    const float dy1 = floorf(dyf);
    const float dx1 = floorf(dxf);
    const float fy  = dyf - dy1;
    const float fx  = dxf - dx1;
    const int   iy1 = (int)dy1;          // >= 0
    const int   ix1 = (int)dx1;          // may be negative

    const int hp   = HH - 1 - iy1;
    const int x_lo = max(0, -ix1);
    const int x_hi = min(WW, WW - 1 - ix1);

    const float w11 = (1.0f - fx) * (1.0f - fy);
    const float w12 = fx * (1.0f - fy);
    const float w21 = (1.0f - fx) * fy;
    const float w22 = fx * fy;

    const float* f0  = Flow + (size_t)b * 2 * HH * WW;
    const float* f1  = f0 + HH * WW;
    const float* m0p = Mask + (size_t)b * 2 * HH * WW;
    const float* m1p = m0p + HH * WW;

    // thread layout: 128 x-groups (4 px each) x 2 y-lanes
    const int x0    = (threadIdx.x & 127) * 4;
    const int ylane = threadIdx.x >> 7;

    float acc = 0.0f;

    #pragma unroll
    for (int r = 0; r < 8; r += 2) {
        const int y   = row0 + r + ylane;
        const int gy1 = min(y + iy1, HH - 1);
        const int gy2 = min(y + iy1 + 1, HH - 1);
        const bool yv = (y < hp);

        // 5 consecutive (clamped) samples per row per channel serve all 4 px.
        float t0[5], u0[5], t1[5], u1[5];
        #pragma unroll
        for (int i = 0; i < 5; i++) {
            const int gx = min(max(x0 + ix1 + i, 0), WW - 1);
            t0[i] = __ldg(f0 + gy1 * WW + gx);
            u0[i] = __ldg(f0 + gy2 * WW + gx);
            t1[i] = __ldg(f1 + gy1 * WW + gx);
            u1[i] = __ldg(f1 + gy2 * WW + gx);
        }

        const float4 c0 = *reinterpret_cast<const float4*>(f0  + y * WW + x0);
        const float4 c1 = *reinterpret_cast<const float4*>(f1  + y * WW + x0);
        const float4 q0 = *reinterpret_cast<const float4*>(m0p + y * WW + x0);
        const float4 q1 = *reinterpret_cast<const float4*>(m1p + y * WW + x0);
        const float c0a[4] = {c0.x, c0.y, c0.z, c0.w};
        const float c1a[4] = {c1.x, c1.y, c1.z, c1.w};
        const float q0a[4] = {q0.x, q0.y, q0.z, q0.w};
        const float q1a[4] = {q1.x, q1.y, q1.z, q1.w};

        #pragma unroll
        for (int j = 0; j < 4; j++) {
            const float ph0 = w11 * t0[j] + w12 * t0[j + 1]
                            + w21 * u0[j] + w22 * u0[j + 1];
            const float ph1 = w11 * t1[j] + w12 * t1[j + 1]
                            + w21 * u1[j] + w22 * u1[j + 1];
            const float d0 = c0a[j] - ph0;
            const float d1 = c1a[j] - ph1;
            const float s  = d1 * sb0 - d0 * sb1;
            const int  xx  = x0 + j;
            const float v  = (yv && xx >= x_lo && xx < x_hi) ? 1.0f : 0.0f;
            acc += (q0a[j] + q1a[j]) * (s * s) * v;
        }
    }

    // ---- reduction: warp shuffle -> shared -> one atomic per block ----
    #pragma unroll
    for (int o = 16; o; o >>= 1)
        acc += __shfl_xor_sync(0xffffffffu, acc, o);

    __shared__ float sred[8];
    const int wid = threadIdx.x >> 5;
    const int lid = threadIdx.x & 31;
    if (lid == 0) sred[wid] = acc;
    __syncthreads();

    if (threadIdx.x == 0) {
        float s = 0.0f;
        #pragma unroll
        for (int i = 0; i < 8; i++) s += sred[i];
        const float denom = 2.0f * (float)max(hp, 1)
                          * (float)max(x_hi - x_lo, 1) * (float)BN;
        atomicAdd(out, s / denom);
    }
}

extern "C" void kernel_launch(void* const* d_in, const int* in_sizes, int n_in,
                              void* d_out, int out_size)
{
    const float* Flow = (const float*)d_in[0];
    const float* Asym = (const float*)d_in[1];
    const float* Bsym = (const float*)d_in[2];
    const float* Mask = (const float*)d_in[3];
    float* out = (float*)d_out;

    sym_zero_out<<<1, 1>>>(out);
    dim3 grid(HH / 8, BN);
    symloss_kernel<<<grid, 256>>>(Flow, Asym, Bsym, Mask, out);
}

// round 2
// speedup vs baseline: 1.0463x; 1.0463x over previous
#include <cuda_runtime.h>

// SymLoss: B=32, Flow/Mask (B,2,512,512) f32, A/B axes (B,2) f32.
// loss = (1/B) * sum_b num_b / denom_b
//   num_b = sum_{c,y,x} mask[c] * ((dphi1*b0 - dphi0*b1)^2) * valid
//   dphi  = flow - bilinear(flow shifted by (dy,dx))
// Shifted-row reads use aligned float4 windows (misalignment o = ix1 & 3 is
// block-uniform -> 4-way compile-time dispatch, no register spills).

#define HH 512
#define WW 512
#define BN 32

__global__ void sym_zero_out(float* out) { out[0] = 0.0f; }

__device__ __forceinline__ void loadwin(const float* __restrict__ rowp,
                                        int gxb, bool safe, float* w)
{
    if (safe) {
        const float4 a = __ldg(reinterpret_cast<const float4*>(rowp + gxb));
        const float4 b = __ldg(reinterpret_cast<const float4*>(rowp + gxb + 4));
        w[0] = a.x; w[1] = a.y; w[2] = a.z; w[3] = a.w;
        w[4] = b.x; w[5] = b.y; w[6] = b.z; w[7] = b.w;
    } else {
        #pragma unroll
        for (int i = 0; i < 8; i++) {
            const int gx = min(max(gxb + i, 0), WW - 1);
            w[i] = __ldg(rowp + gx);
        }
    }
}

template <int O>
__device__ __forceinline__ float sym_body(
    const float* __restrict__ f0, const float* __restrict__ f1,
    const float* __restrict__ m0p, const float* __restrict__ m1p,
    int row0, int ylane, int x0, int gxb, bool safe,
    int iy1, int hp, int x_lo, int x_hi,
    float w11, float w12, float w21, float w22, float sb0, float sb1)
{
    float acc = 0.0f;

    #pragma unroll
    for (int r = 0; r < 8; r += 2) {
        const int y = row0 + r + ylane;
        if (y >= hp) continue;                  // warp-uniform: no contribution
        const int gy1 = min(y + iy1, HH - 1);
        const int gy2 = min(y + iy1 + 1, HH - 1);

        // combined mask (channel-independent sq) x validity
        const float4 q0 = __ldg(reinterpret_cast<const float4*>(m0p + y * WW + x0));
        const float4 q1 = __ldg(reinterpret_cast<const float4*>(m1p + y * WW + x0));
        float mm[4] = {q0.x + q1.x, q0.y + q1.y, q0.z + q1.z, q0.w + q1.w};
        #pragma unroll
        for (int j = 0; j < 4; j++) {
            const int xx = x0 + j;
            if (xx < x_lo || xx >= x_hi) mm[j] = 0.0f;
        }

        float t[8], u[8];

        // ---- channel 0 ----
        loadwin(f0 + gy1 * WW, gxb, safe, t);
        loadwin(f0 + gy2 * WW, gxb, safe, u);
        const float4 c0 = __ldg(reinterpret_cast<const float4*>(f0 + y * WW + x0));
        const float c0a[4] = {c0.x, c0.y, c0.z, c0.w};
        float d0[4];
        #pragma unroll
        for (int j = 0; j < 4; j++) {
            const float ph = w11 * t[O + j] + w12 * t[O + j + 1]
                           + w21 * u[O + j] + w22 * u[O + j + 1];
            d0[j] = c0a[j] - ph;
        }

        // ---- channel 1 ----
        loadwin(f1 + gy1 * WW, gxb, safe, t);
        loadwin(f1 + gy2 * WW, gxb, safe, u);
        const float4 c1 = __ldg(reinterpret_cast<const float4*>(f1 + y * WW + x0));
        const float c1a[4] = {c1.x, c1.y, c1.z, c1.w};
        #pragma unroll
        for (int j = 0; j < 4; j++) {
            const float ph = w11 * t[O + j] + w12 * t[O + j + 1]
                           + w21 * u[O + j] + w22 * u[O + j + 1];
            const float d1 = c1a[j] - ph;
            const float s  = d1 * sb0 - d0[j] * sb1;
            acc += mm[j] * (s * s);
        }
    }
    return acc;
}

__global__ __launch_bounds__(256) void symloss_kernel(
    const float* __restrict__ Flow,
    const float* __restrict__ Asym,
    const float* __restrict__ Bsym,
    const float* __restrict__ Mask,
    float* __restrict__ out)
{
    const int b    = blockIdx.y;
    const int row0 = blockIdx.x * 8;

    const float a0  = __ldg(Asym + 2 * b);
    const float a1  = __ldg(Asym + 2 * b + 1);
    const float sb0 = __ldg(Bsym + 2 * b);
    const float sb1 = __ldg(Bsym + 2 * b + 1);

    const float dxf = -3.0f * a0;
    const float dyf = fabsf(3.0f * a1);
    const float dy1 = floorf(dyf);
    const float dx1 = floorf(dxf);
    const float fy  = dyf - dy1;
    const float fx  = dxf - dx1;
    const int   iy1 = (int)dy1;          // >= 0
    const int   ix1 = (int)dx1;          // may be negative

    const int hp   = HH - 1 - iy1;
    const int x_lo = max(0, -ix1);
    const int x_hi = min(WW, WW - 1 - ix1);

    const float w11 = (1.0f - fx) * (1.0f - fy);
    const float w12 = fx * (1.0f - fy);
    const float w21 = (1.0f - fx) * fy;
    const float w22 = fx * fy;

    const float* f0  = Flow + (size_t)b * 2 * HH * WW;
    const float* f1  = f0 + HH * WW;
    const float* m0p = Mask + (size_t)b * 2 * HH * WW;
    const float* m1p = m0p + HH * WW;

    // thread layout: 128 x-groups (4 px each) x 2 y-lanes
    const int x0    = (threadIdx.x & 127) * 4;
    const int ylane = threadIdx.x >> 7;

    const int  o    = ix1 & 3;                 // block-uniform misalignment
    const int  gxb  = x0 + (ix1 & ~3);         // 16B-aligned window base
    const bool safe = (gxb >= 0) && (gxb + 8 <= WW);

    float acc;
    switch (o) {                               // block-uniform branch
    case 0: acc = sym_body<0>(f0, f1, m0p, m1p, row0, ylane, x0, gxb, safe,
                              iy1, hp, x_lo, x_hi, w11, w12, w21, w22, sb0, sb1); break;
    case 1: acc = sym_body<1>(f0, f1, m0p, m1p, row0, ylane, x0, gxb, safe,
                              iy1, hp, x_lo, x_hi, w11, w12, w21, w22, sb0, sb1); break;
    case 2: acc = sym_body<2>(f0, f1, m0p, m1p, row0, ylane, x0, gxb, safe,
                              iy1, hp, x_lo, x_hi, w11, w12, w21, w22, sb0, sb1); break;
    default: acc = sym_body<3>(f0, f1, m0p, m1p, row0, ylane, x0, gxb, safe,
                              iy1, hp, x_lo, x_hi, w11, w12, w21, w22, sb0, sb1); break;
    }

    // ---- reduction: warp shuffle -> shared -> one atomic per block ----
    #pragma unroll
    for (int off = 16; off; off >>= 1)
        acc += __shfl_xor_sync(0xffffffffu, acc, off);

    __shared__ float sred[8];
    const int wid = threadIdx.x >> 5;
    const int lid = threadIdx.x & 31;
    if (lid == 0) sred[wid] = acc;
    __syncthreads();

    if (threadIdx.x == 0) {
        float s = 0.0f;
        #pragma unroll
        for (int i = 0; i < 8; i++) s += sred[i];
        const float denom = 2.0f * (float)max(hp, 1)
                          * (float)max(x_hi - x_lo, 1) * (float)BN;
        atomicAdd(out, s / denom);
    }
}

extern "C" void kernel_launch(void* const* d_in, const int* in_sizes, int n_in,
                              void* d_out, int out_size)
{
    const float* Flow = (const float*)d_in[0];
    const float* Asym = (const float*)d_in[1];
    const float* Bsym = (const float*)d_in[2];
    const float* Mask = (const float*)d_in[3];
    float* out = (float*)d_out;

    sym_zero_out<<<1, 1>>>(out);
    dim3 grid(HH / 8, BN);
    symloss_kernel<<<grid, 256>>>(Flow, Asym, Bsym, Mask, out);
}

// round 3
// speedup vs baseline: 1.0588x; 1.0119x over previous
#include <cuda_runtime.h>

// SymLoss: B=32, Flow/Mask (B,2,512,512) f32, A/B axes (B,2) f32.
// loss = (1/B) * sum_b num_b / denom_b
//   num_b = sum_{c,y,x} mask[c] * ((dphi1*b0 - dphi0*b1)^2) * valid
//   dphi  = flow - bilinear(flow shifted by (dy,dx))
//
// R3: each thread walks 4 CONSECUTIVE rows so the bottom bilinear window of
// row y is reused as the top window of row y+1 (gy2(y)==gy1(y+1)), and the
// unrolled chain lets ptxas front-batch LDGs for higher MLP.

#define HH 512
#define WW 512
#define BN 32

__global__ void sym_zero_out(float* out) { out[0] = 0.0f; }

__device__ __forceinline__ void loadwin(const float* __restrict__ rowp,
                                        int gxb, bool safe, float* w)
{
    if (safe) {
        const float4 a = __ldg(reinterpret_cast<const float4*>(rowp + gxb));
        const float4 b = __ldg(reinterpret_cast<const float4*>(rowp + gxb + 4));
        w[0] = a.x; w[1] = a.y; w[2] = a.z; w[3] = a.w;
        w[4] = b.x; w[5] = b.y; w[6] = b.z; w[7] = b.w;
    } else {
        #pragma unroll
        for (int i = 0; i < 8; i++) {
            const int gx = min(max(gxb + i, 0), WW - 1);
            w[i] = __ldg(rowp + gx);
        }
    }
}

template <int O>
__device__ __forceinline__ float sym_body(
    const float* __restrict__ f0, const float* __restrict__ f1,
    const float* __restrict__ m0p, const float* __restrict__ m1p,
    int y0, int x0, int gxb, bool safe,
    int iy1, int hp, int x_lo, int x_hi,
    float w11, float w12, float w21, float w22, float sb0, float sb1)
{
    float acc = 0.0f;

    // x-validity is row-independent: hoist it.
    float xm[4];
    #pragma unroll
    for (int j = 0; j < 4; j++) {
        const int xx = x0 + j;
        xm[j] = (xx >= x_lo && xx < x_hi) ? 1.0f : 0.0f;
    }

    float t0[8], t1[8], u0[8], u1[8];
    {
        const int gy = min(y0 + iy1, HH - 1);
        loadwin(f0 + gy * WW, gxb, safe, t0);
        loadwin(f1 + gy * WW, gxb, safe, t1);
    }

    #pragma unroll
    for (int r = 0; r < 4; r++) {
        const int y = y0 + r;
        if (y >= hp) break;                       // rows ascend: rest invalid
        const int gy2 = min(y + iy1 + 1, HH - 1);

        loadwin(f0 + gy2 * WW, gxb, safe, u0);
        loadwin(f1 + gy2 * WW, gxb, safe, u1);

        const float4 q0 = __ldg(reinterpret_cast<const float4*>(m0p + y * WW + x0));
        const float4 q1 = __ldg(reinterpret_cast<const float4*>(m1p + y * WW + x0));
        const float4 c0 = __ldg(reinterpret_cast<const float4*>(f0  + y * WW + x0));
        const float4 c1 = __ldg(reinterpret_cast<const float4*>(f1  + y * WW + x0));

        const float mm[4]  = {(q0.x + q1.x) * xm[0], (q0.y + q1.y) * xm[1],
                              (q0.z + q1.z) * xm[2], (q0.w + q1.w) * xm[3]};
        const float c0a[4] = {c0.x, c0.y, c0.z, c0.w};
        const float c1a[4] = {c1.x, c1.y, c1.z, c1.w};

        #pragma unroll
        for (int j = 0; j < 4; j++) {
            const float ph0 = w11 * t0[O + j] + w12 * t0[O + j + 1]
                            + w21 * u0[O + j] + w22 * u0[O + j + 1];
            const float ph1 = w11 * t1[O + j] + w12 * t1[O + j + 1]
                            + w21 * u1[O + j] + w22 * u1[O + j + 1];
            const float d0 = c0a[j] - ph0;
            const float d1 = c1a[j] - ph1;
            const float s  = d1 * sb0 - d0 * sb1;
            acc = fmaf(mm[j] * s, s, acc);
        }

        #pragma unroll
        for (int i = 0; i < 8; i++) { t0[i] = u0[i]; t1[i] = u1[i]; }
    }
    return acc;
}

__global__ __launch_bounds__(256) void symloss_kernel(
    const float* __restrict__ Flow,
    const float* __restrict__ Asym,
    const float* __restrict__ Bsym,
    const float* __restrict__ Mask,
    float* __restrict__ out)
{
    const int b    = blockIdx.y;
    const int row0 = blockIdx.x * 8;

    const float a0  = __ldg(Asym + 2 * b);
    const float a1  = __ldg(Asym + 2 * b + 1);
    const float sb0 = __ldg(Bsym + 2 * b);
    const float sb1 = __ldg(Bsym + 2 * b + 1);

    const float dxf = -3.0f * a0;
    const float dyf = fabsf(3.0f * a1);
    const float dy1 = floorf(dyf);
    const float dx1 = floorf(dxf);
    const float fy  = dyf - dy1;
    const float fx  = dxf - dx1;
    const int   iy1 = (int)dy1;          // >= 0
    const int   ix1 = (int)dx1;          // may be negative

    const int hp   = HH - 1 - iy1;
    const int x_lo = max(0, -ix1);
    const int x_hi = min(WW, WW - 1 - ix1);

    const float w11 = (1.0f - fx) * (1.0f - fy);
    const float w12 = fx * (1.0f - fy);
    const float w21 = (1.0f - fx) * fy;
    const float w22 = fx * fy;

    const float* f0  = Flow + (size_t)b * 2 * HH * WW;
    const float* f1  = f0 + HH * WW;
    const float* m0p = Mask + (size_t)b * 2 * HH * WW;
    const float* m1p = m0p + HH * WW;

    // 128 x-groups (4 px each) x 2 y-halves; each thread walks 4 consecutive rows
    const int x0 = (threadIdx.x & 127) * 4;
    const int y0 = row0 + (threadIdx.x >> 7) * 4;

    const int  o    = ix1 & 3;                 // block-uniform misalignment
    const int  gxb  = x0 + (ix1 & ~3);         // 16B-aligned window base
    const bool safe = (gxb >= 0) && (gxb + 8 <= WW);

    float acc;
    switch (o) {                               // block-uniform branch
    case 0: acc = sym_body<0>(f0, f1, m0p, m1p, y0, x0, gxb, safe,
                              iy1, hp, x_lo, x_hi, w11, w12, w21, w22, sb0, sb1); break;
    case 1: acc = sym_body<1>(f0, f1, m0p, m1p, y0, x0, gxb, safe,
                              iy1, hp, x_lo, x_hi, w11, w12, w21, w22, sb0, sb1); break;
    case 2: acc = sym_body<2>(f0, f1, m0p, m1p, y0, x0, gxb, safe,
                              iy1, hp, x_lo, x_hi, w11, w12, w21, w22, sb0, sb1); break;
    default: acc = sym_body<3>(f0, f1, m0p, m1p, y0, x0, gxb, safe,
                              iy1, hp, x_lo, x_hi, w11, w12, w21, w22, sb0, sb1); break;
    }

    // ---- reduction: warp shuffle -> shared -> one atomic per block ----
    #pragma unroll
    for (int off = 16; off; off >>= 1)
        acc += __shfl_xor_sync(0xffffffffu, acc, off);

    __shared__ float sred[8];
    const int wid = threadIdx.x >> 5;
    const int lid = threadIdx.x & 31;
    if (lid == 0) sred[wid] = acc;
    __syncthreads();

    if (threadIdx.x == 0) {
        float s = 0.0f;
        #pragma unroll
        for (int i = 0; i < 8; i++) s += sred[i];
        const float denom = 2.0f * (float)max(hp, 1)
                          * (float)max(x_hi - x_lo, 1) * (float)BN;
        atomicAdd(out, s / denom);
    }
}

extern "C" void kernel_launch(void* const* d_in, const int* in_sizes, int n_in,
                              void* d_out, int out_size)
{
    const float* Flow = (const float*)d_in[0];
    const float* Asym = (const float*)d_in[1];
    const float* Bsym = (const float*)d_in[2];
    const float* Mask = (const float*)d_in[3];
    float* out = (float*)d_out;

    sym_zero_out<<<1, 1>>>(out);
    dim3 grid(HH / 8, BN);
    symloss_kernel<<<grid, 256>>>(Flow, Asym, Bsym, Mask, out);
}